// round 5
// baseline (speedup 1.0000x reference)
#include <cuda_runtime.h>
#include <cuda_bf16.h>
#include <cstdint>

#define NPTS 16384
#define ODIM 128
#define KNN  16
#define NCAND 24
#define NBLK 128          // 16384 / 128

// ---------------- scratch (no allocation allowed) ----------------
__device__ float g_base[NPTS * ODIM];              // x @ (W1a - W1b) + b1
__device__ float g_Bv[NPTS * ODIM];                // x @ W1b
__device__ __align__(16) float g_sq[NPTS];         // |x|^2
__device__ int   g_idx[NPTS * KNN];                // final knn indices
__device__ int   g_cand[NPTS * NCAND];             // coarse candidates
__device__ __align__(16) unsigned g_Af[NBLK * 4096];  // A fragments (bf16 hi)
__device__ __align__(16) unsigned g_Bf[NBLK * 4096];  // B fragments (bf16 hi)

// =================================================================
// precompute: base, Bv, sq.  4 points per block, 128 threads (o=tid)
// =================================================================
__global__ void __launch_bounds__(128) precompute_kernel(
    const float* __restrict__ x, const float* __restrict__ W1,
    const float* __restrict__ b1)
{
    const int n0  = blockIdx.x * 4;
    const int tid = threadIdx.x;
    __shared__ float xs[4][64];

    #pragma unroll
    for (int r = 0; r < 2; r++) {
        int li = r * 128 + tid;
        xs[li >> 6][li & 63] = x[n0 * 64 + li];
    }
    __syncthreads();

    float a1[4] = {0.f, 0.f, 0.f, 0.f};
    float a2[4] = {0.f, 0.f, 0.f, 0.f};
    #pragma unroll 4
    for (int c = 0; c < 64; c++) {
        float wa = W1[c * 128 + tid];
        float wb = W1[(64 + c) * 128 + tid];
        float wd = wa - wb;
        #pragma unroll
        for (int nn = 0; nn < 4; nn++) {
            float xv = xs[nn][c];
            a1[nn] = fmaf(xv, wd, a1[nn]);
            a2[nn] = fmaf(xv, wb, a2[nn]);
        }
    }
    float bb = b1[tid];
    #pragma unroll
    for (int nn = 0; nn < 4; nn++) {
        g_base[(n0 + nn) * 128 + tid] = a1[nn] + bb;
        g_Bv[(n0 + nn) * 128 + tid]  = a2[nn];
    }

    int w = tid >> 5, lane = tid & 31;
    float v = xs[w][lane] * xs[w][lane] + xs[w][lane + 32] * xs[w][lane + 32];
    #pragma unroll
    for (int off = 16; off > 0; off >>= 1)
        v += __shfl_xor_sync(0xffffffffu, v, off);
    if (lane == 0) g_sq[n0 + w] = v;
}

// =================================================================
// fragpack: bf16(hi) of x into mma fragment order (per 128-pt block).
// A frag u32 idx: (ks*8+mt)*128 + la*4 + rA     (4*8*128 = 4096)
// B frag u32 idx: (ks*16+nt)*64 + la*2 + r1     (4*16*64 = 4096)
// m16n8k16: la = g*4+cb (g=row&7, cb=(k>>1)&3)
//   A: rA = ((k>>3)&1)*2 + ((row>>3)&1)   B: r1 = (k>>3)&1
// =================================================================
__global__ void __launch_bounds__(256) fragpack_kernel(const float* __restrict__ x)
{
    __shared__ unsigned sA[4096];
    __shared__ unsigned sB[4096];

    const int blk = blockIdx.x;
    const int tid = threadIdx.x;
    const int rl  = tid >> 1;            // local point 0..127
    const int c0  = (tid & 1) * 32;      // column half

    float v[32];
    const float4* xr = (const float4*)(x + (blk * 128 + rl) * 64 + c0);
    #pragma unroll
    for (int i = 0; i < 8; i++) {
        float4 t = xr[i];
        v[i * 4 + 0] = t.x; v[i * 4 + 1] = t.y;
        v[i * 4 + 2] = t.z; v[i * 4 + 3] = t.w;
    }

    const int mt = rl >> 4, gid = rl & 7, r0 = (rl >> 3) & 1;
    const int nt = rl >> 3;
    const int l  = gid * 4;

    #pragma unroll
    for (int cc = 0; cc < 32; cc += 2) {
        int c = c0 + cc;
        __nv_bfloat16 h0 = __float2bfloat16(v[cc]);
        __nv_bfloat16 h1 = __float2bfloat16(v[cc + 1]);
        unsigned uhi = ((unsigned)__bfloat16_as_ushort(h1) << 16) | __bfloat16_as_ushort(h0);

        int ks = c >> 4, cb = (c >> 1) & 3, r1 = (c >> 3) & 1;
        int la = l + cb;
        int rA = r1 * 2 + r0;
        sA[(ks * 8 + mt) * 128 + la * 4 + rA] = uhi;
        sB[(ks * 16 + nt) * 64 + la * 2 + r1] = uhi;
    }
    __syncthreads();

    uint4* dA = (uint4*)(g_Af + blk * 4096);
    uint4* dB = (uint4*)(g_Bf + blk * 4096);
    const uint4* s4A = (const uint4*)sA;
    const uint4* s4B = (const uint4*)sB;
    #pragma unroll
    for (int i = 0; i < 4; i++) {
        dA[i * 256 + tid] = s4A[i * 256 + tid];
        dB[i * 256 + tid] = s4B[i * 256 + tid];
    }
}

// =================================================================
// coarse kNN via bf16 mma.sync (hi-only, fp32 accum).
// CTA: 128 queries x 128-j tiles. 8 warps, each 64x32. top-24/query.
// =================================================================
// smem u32 layout:
#define OFF_B   4096            // B double buffer: 2 x 4096
#define OFF_SQ  12288           // 2 x 128 floats
#define OFF_DST 12544           // 128 x 132 floats
#define SM_U32  29440
#define SM_BYTES (SM_U32 * 4)
#define DSTR 132

#define TOPK_INSERT(valx, jjx) do {                                        \
    float _d = (valx); int _j = (jjx);                                     \
    if (_d < kd[NCAND - 1]) {                                              \
        _Pragma("unroll")                                                  \
        for (int _m = 0; _m < NCAND; _m++) {                               \
            if (_d < kd[_m]) {                                             \
                float _td = kd[_m]; kd[_m] = _d; _d = _td;                 \
                int   _tj = ki[_m]; ki[_m] = _j; _j = _tj;                 \
            }                                                              \
        }                                                                  \
    }                                                                      \
} while (0)

__device__ __forceinline__ void cp16(unsigned saddr, const void* g)
{
    asm volatile("cp.async.cg.shared.global [%0], [%1], 16;" :: "r"(saddr), "l"(g));
}

__global__ void __launch_bounds__(256, 1) knn_kernel()
{
    extern __shared__ __align__(16) unsigned sm[];
    float* dstf = (float*)(sm + OFF_DST);

    const int tid  = threadIdx.x;
    const int lane = tid & 31;
    const int wid  = tid >> 5;
    const int wm   = wid >> 2;       // m-block of 64 rows
    const int wn   = wid & 3;        // n-block of 32 cols
    const unsigned smbase = (unsigned)__cvta_generic_to_shared(sm);

    // ---- initial loads: A block + B tile 0 + sq 0 ----
    {
        const uint4* gA = (const uint4*)(g_Af + blockIdx.x * 4096);
        #pragma unroll
        for (int i = 0; i < 4; i++)
            cp16(smbase + (i * 256 + tid) * 16, gA + i * 256 + tid);
        const uint4* gB = (const uint4*)(g_Bf);
        #pragma unroll
        for (int i = 0; i < 4; i++)
            cp16(smbase + OFF_B * 4 + (i * 256 + tid) * 16, gB + i * 256 + tid);
        if (tid < 32)
            cp16(smbase + OFF_SQ * 4 + tid * 16, g_sq + tid * 4);
    }
    asm volatile("cp.async.commit_group;");

    float kd[NCAND]; int ki[NCAND];
    #pragma unroll
    for (int m = 0; m < NCAND; m++) { kd[m] = 1e30f; ki[m] = 0; }

    const int qh = tid & 1;          // which half of the row to scan
    const int qq = tid >> 1;         // query row

    for (int jt = 0; jt < NBLK; jt++) {
        const int cur = jt & 1;
        // ---- prefetch next B tile ----
        if (jt + 1 < NBLK) {
            const uint4* gB = (const uint4*)(g_Bf + (jt + 1) * 4096);
            #pragma unroll
            for (int i = 0; i < 4; i++)
                cp16(smbase + (OFF_B + ((jt + 1) & 1) * 4096) * 4 + (i * 256 + tid) * 16,
                     gB + i * 256 + tid);
            if (tid < 32)
                cp16(smbase + (OFF_SQ + ((jt + 1) & 1) * 128) * 4 + tid * 16,
                     g_sq + (jt + 1) * 128 + tid * 4);
        }
        asm volatile("cp.async.commit_group;");
        asm volatile("cp.async.wait_group 1;");
        __syncthreads();

        // ---- MMA: 4 k-steps, hi x hi ----
        float acc[4][4][4];
        #pragma unroll
        for (int mi = 0; mi < 4; mi++)
            #pragma unroll
            for (int ni = 0; ni < 4; ni++)
                #pragma unroll
                for (int r = 0; r < 4; r++) acc[mi][ni][r] = 0.f;

        #pragma unroll
        for (int ks = 0; ks < 4; ks++) {
            const uint4* Ab = (const uint4*)(sm + (ks * 8 + wm * 4) * 128);
            const uint2* Bb = (const uint2*)(sm + OFF_B + cur * 4096 +
                                             (ks * 16 + wn * 4) * 64);
            unsigned a[4][4], b[4][2];
            #pragma unroll
            for (int mi = 0; mi < 4; mi++) {
                uint4 t = Ab[mi * 32 + lane];
                a[mi][0] = t.x; a[mi][1] = t.y; a[mi][2] = t.z; a[mi][3] = t.w;
            }
            #pragma unroll
            for (int ni = 0; ni < 4; ni++) {
                uint2 t = Bb[ni * 32 + lane];
                b[ni][0] = t.x; b[ni][1] = t.y;
            }
            #pragma unroll
            for (int mi = 0; mi < 4; mi++)
                #pragma unroll
                for (int ni = 0; ni < 4; ni++)
                    asm volatile(
                        "mma.sync.aligned.m16n8k16.row.col.f32.bf16.bf16.f32 "
                        "{%0,%1,%2,%3}, {%4,%5,%6,%7}, {%8,%9}, {%0,%1,%2,%3};"
                        : "+f"(acc[mi][ni][0]), "+f"(acc[mi][ni][1]),
                          "+f"(acc[mi][ni][2]), "+f"(acc[mi][ni][3])
                        : "r"(a[mi][0]), "r"(a[mi][1]), "r"(a[mi][2]), "r"(a[mi][3]),
                          "r"(b[ni][0]), "r"(b[ni][1]));
        }

        // ---- epilogue: score = 0.5*|xj|^2 - dot, stage to smem ----
        const float* sqb = (const float*)(sm + OFF_SQ + cur * 128);
        const int g  = lane >> 2;
        const int c2 = (lane & 3) * 2;
        #pragma unroll
        for (int mi = 0; mi < 4; mi++) {
            #pragma unroll
            for (int ni = 0; ni < 4; ni++) {
                int row = (wm * 4 + mi) * 16 + g;
                int col = (wn * 4 + ni) * 8 + c2;
                float q0 = 0.5f * sqb[col], q1 = 0.5f * sqb[col + 1];
                float2 s0 = make_float2(q0 - acc[mi][ni][0], q1 - acc[mi][ni][1]);
                float2 s1 = make_float2(q0 - acc[mi][ni][2], q1 - acc[mi][ni][3]);
                *(float2*)&dstf[row * DSTR + col] = s0;
                *(float2*)&dstf[(row + 8) * DSTR + col] = s1;
            }
        }
        __syncthreads();

        // ---- scan my 64-wide half-row, maintain top-24 ----
        const int j0 = jt * 128;
        #pragma unroll
        for (int m4 = 0; m4 < 16; m4++) {
            float4 v = *(const float4*)&dstf[qq * DSTR + qh * 64 + m4 * 4];
            int jb = j0 + qh * 64 + m4 * 4;
            TOPK_INSERT(v.x, jb + 0);
            TOPK_INSERT(v.y, jb + 1);
            TOPK_INSERT(v.z, jb + 2);
            TOPK_INSERT(v.w, jb + 3);
        }
        __syncthreads();
    }

    // ---- merge the 2 sorted 24-lists per query -> top-24 ----
    float* candd = dstf;                       // 256*24 floats
    int*   candi = (int*)(dstf + 6144);        // 256*24 ints
    #pragma unroll
    for (int m = 0; m < NCAND; m++) {
        candd[tid * NCAND + m] = kd[m];
        candi[tid * NCAND + m] = ki[m];
    }
    __syncthreads();
    if (tid < 128) {
        int p0 = 0, p1 = 0;
        const int ob = (blockIdx.x * 128 + tid) * NCAND;
        #pragma unroll
        for (int m = 0; m < NCAND; m++) {
            float v0 = candd[(tid * 2) * NCAND + p0];
            float v1 = candd[(tid * 2 + 1) * NCAND + p1];
            if (v0 <= v1) { g_cand[ob + m] = candi[(tid * 2) * NCAND + p0]; p0++; }
            else          { g_cand[ob + m] = candi[(tid * 2 + 1) * NCAND + p1]; p1++; }
        }
    }
}

// =================================================================
// refine: exact fp32 re-score of 24 candidates, select true top-16.
// 4 queries per block (1 warp each), lane = candidate.
// =================================================================
__global__ void __launch_bounds__(128) refine_kernel(const float* __restrict__ x)
{
    __shared__ float xi[4][64];
    const int tid = threadIdx.x;
    const int w   = tid >> 5, lane = tid & 31;
    const int q0  = blockIdx.x * 4;

    #pragma unroll
    for (int r = 0; r < 2; r++) {
        int li = r * 128 + tid;
        xi[li >> 6][li & 63] = x[q0 * 64 + li];
    }
    __syncthreads();

    const int q = q0 + w;
    int cj = 0;
    float s = 1e30f;
    if (lane < NCAND) {
        cj = g_cand[q * NCAND + lane];
        const float4* xr = (const float4*)(x + cj * 64);
        float dot = 0.f;
        #pragma unroll
        for (int i = 0; i < 16; i++) {
            float4 v = xr[i];
            dot = fmaf(xi[w][i * 4 + 0], v.x, dot);
            dot = fmaf(xi[w][i * 4 + 1], v.y, dot);
            dot = fmaf(xi[w][i * 4 + 2], v.z, dot);
            dot = fmaf(xi[w][i * 4 + 3], v.w, dot);
        }
        s = fmaf(0.5f, g_sq[cj], -dot);
    }

    int rank = 0;
    #pragma unroll
    for (int m = 0; m < NCAND; m++) {
        float sv = __shfl_sync(0xffffffffu, s, m);
        rank += (sv < s) || (sv == s && m < lane);
    }
    if (lane < NCAND && rank < KNN)
        g_idx[q * KNN + rank] = cj;
}

// =================================================================
// aggregate: s = mean_k relu(base + Bv[j_k]);  out = s @ W2 + b2
// 8 points per block, 128 threads (o = tid), W2 read coalesced.
// =================================================================
__global__ void __launch_bounds__(128) aggregate_kernel(
    const float* __restrict__ W2, const float* __restrict__ b2,
    float* __restrict__ out)
{
    const int n0  = blockIdx.x * 8;
    const int tid = threadIdx.x;
    __shared__ float ss[8][128];
    __shared__ int sidx[128];

    sidx[tid] = g_idx[n0 * 16 + tid];
    __syncthreads();

    #pragma unroll
    for (int p = 0; p < 8; p++) {
        float bv  = g_base[(n0 + p) * 128 + tid];
        float acc = 0.f;
        #pragma unroll
        for (int k = 0; k < 16; k++) {
            float v = bv + g_Bv[sidx[p * 16 + k] * 128 + tid];
            acc += fmaxf(v, 0.f);
        }
        ss[p][tid] = acc * (1.0f / 16.0f);
    }
    __syncthreads();

    float r[8];
    float bb = b2[tid];
    #pragma unroll
    for (int p = 0; p < 8; p++) r[p] = bb;

    #pragma unroll 4
    for (int i = 0; i < 128; i++) {
        float w = W2[i * 128 + tid];
        #pragma unroll
        for (int p = 0; p < 8; p++)
            r[p] = fmaf(ss[p][i], w, r[p]);
    }
    #pragma unroll
    for (int p = 0; p < 8; p++)
        out[(n0 + p) * 128 + tid] = r[p];
}

// =================================================================
extern "C" void kernel_launch(void* const* d_in, const int* in_sizes, int n_in,
                              void* d_out, int out_size)
{
    const float* x  = (const float*)d_in[0];
    const float* W1 = (const float*)d_in[1];
    const float* b1 = (const float*)d_in[2];
    const float* W2 = (const float*)d_in[3];
    const float* b2 = (const float*)d_in[4];
    float* out = (float*)d_out;

    cudaFuncSetAttribute(knn_kernel,
                         cudaFuncAttributeMaxDynamicSharedMemorySize, SM_BYTES);

    precompute_kernel<<<NPTS / 4, 128>>>(x, W1, b1);
    fragpack_kernel<<<NBLK, 256>>>(x);
    knn_kernel<<<NBLK, 256, SM_BYTES>>>();
    refine_kernel<<<NPTS / 4, 128>>>(x);
    aggregate_kernel<<<NPTS / 8, 128>>>(W2, b2, out);
}

// round 6
// speedup vs baseline: 1.8460x; 1.8460x over previous
#include <cuda_runtime.h>
#include <cuda_bf16.h>
#include <cstdint>

#define NPTS 16384
#define ODIM 128
#define KNN  16
#define NCAND 32
#define NBLK 128          // 16384 / 128

// ---------------- scratch (no allocation allowed) ----------------
__device__ float g_base[NPTS * ODIM];              // x @ (W1a - W1b) + b1
__device__ float g_Bv[NPTS * ODIM];                // x @ W1b
__device__ __align__(16) float g_sq[NPTS];         // |x|^2
__device__ int   g_idx[NPTS * KNN];                // final knn indices
__device__ int   g_cand[NPTS * NCAND];             // coarse candidates (unsorted)
__device__ __align__(16) unsigned g_Af[NBLK * 4096];  // A fragments (bf16 hi)
__device__ __align__(16) unsigned g_Bf[NBLK * 4096];  // B fragments (bf16 hi)

// =================================================================
// precompute: base, Bv, sq.  4 points per block, 128 threads (o=tid)
// =================================================================
__global__ void __launch_bounds__(128) precompute_kernel(
    const float* __restrict__ x, const float* __restrict__ W1,
    const float* __restrict__ b1)
{
    const int n0  = blockIdx.x * 4;
    const int tid = threadIdx.x;
    __shared__ float xs[4][64];

    #pragma unroll
    for (int r = 0; r < 2; r++) {
        int li = r * 128 + tid;
        xs[li >> 6][li & 63] = x[n0 * 64 + li];
    }
    __syncthreads();

    float a1[4] = {0.f, 0.f, 0.f, 0.f};
    float a2[4] = {0.f, 0.f, 0.f, 0.f};
    #pragma unroll 4
    for (int c = 0; c < 64; c++) {
        float wa = W1[c * 128 + tid];
        float wb = W1[(64 + c) * 128 + tid];
        float wd = wa - wb;
        #pragma unroll
        for (int nn = 0; nn < 4; nn++) {
            float xv = xs[nn][c];
            a1[nn] = fmaf(xv, wd, a1[nn]);
            a2[nn] = fmaf(xv, wb, a2[nn]);
        }
    }
    float bb = b1[tid];
    #pragma unroll
    for (int nn = 0; nn < 4; nn++) {
        g_base[(n0 + nn) * 128 + tid] = a1[nn] + bb;
        g_Bv[(n0 + nn) * 128 + tid]  = a2[nn];
    }

    int w = tid >> 5, lane = tid & 31;
    float v = xs[w][lane] * xs[w][lane] + xs[w][lane + 32] * xs[w][lane + 32];
    #pragma unroll
    for (int off = 16; off > 0; off >>= 1)
        v += __shfl_xor_sync(0xffffffffu, v, off);
    if (lane == 0) g_sq[n0 + w] = v;
}

// =================================================================
// fragpack: bf16(hi) of x into mma fragment order (per 128-pt block).
// =================================================================
__global__ void __launch_bounds__(256) fragpack_kernel(const float* __restrict__ x)
{
    __shared__ unsigned sA[4096];
    __shared__ unsigned sB[4096];

    const int blk = blockIdx.x;
    const int tid = threadIdx.x;
    const int rl  = tid >> 1;
    const int c0  = (tid & 1) * 32;

    float v[32];
    const float4* xr = (const float4*)(x + (blk * 128 + rl) * 64 + c0);
    #pragma unroll
    for (int i = 0; i < 8; i++) {
        float4 t = xr[i];
        v[i * 4 + 0] = t.x; v[i * 4 + 1] = t.y;
        v[i * 4 + 2] = t.z; v[i * 4 + 3] = t.w;
    }

    const int mt = rl >> 4, gid = rl & 7, r0 = (rl >> 3) & 1;
    const int nt = rl >> 3;
    const int l  = gid * 4;

    #pragma unroll
    for (int cc = 0; cc < 32; cc += 2) {
        int c = c0 + cc;
        __nv_bfloat16 h0 = __float2bfloat16(v[cc]);
        __nv_bfloat16 h1 = __float2bfloat16(v[cc + 1]);
        unsigned uhi = ((unsigned)__bfloat16_as_ushort(h1) << 16) | __bfloat16_as_ushort(h0);

        int ks = c >> 4, cb = (c >> 1) & 3, r1 = (c >> 3) & 1;
        int la = l + cb;
        int rA = r1 * 2 + r0;
        sA[(ks * 8 + mt) * 128 + la * 4 + rA] = uhi;
        sB[(ks * 16 + nt) * 64 + la * 2 + r1] = uhi;
    }
    __syncthreads();

    uint4* dA = (uint4*)(g_Af + blk * 4096);
    uint4* dB = (uint4*)(g_Bf + blk * 4096);
    const uint4* s4A = (const uint4*)sA;
    const uint4* s4B = (const uint4*)sB;
    #pragma unroll
    for (int i = 0; i < 4; i++) {
        dA[i * 256 + tid] = s4A[i * 256 + tid];
        dB[i * 256 + tid] = s4B[i * 256 + tid];
    }
}

// =================================================================
// coarse kNN via bf16 mma.sync (hi-only, fp32 accum).
// CTA: 128 queries x 128-j tiles. 8 warps, each 64x32.
// 2 threads/query each keep UNSORTED-output top-16 of their half.
// =================================================================
#define OFF_B   4096            // B double buffer: 2 x 4096 u32
#define OFF_SQ  12288           // 2 x 128 floats
#define OFF_DST 12544           // 128 x 132 floats
#define SM_U32  29440
#define SM_BYTES (SM_U32 * 4)
#define DSTR 132

#define TOPK_INSERT(valx, jjx) do {                                        \
    float _d = (valx); int _j = (jjx);                                     \
    if (_d < kd[15]) {                                                     \
        _Pragma("unroll")                                                  \
        for (int _m = 0; _m < 16; _m++) {                                  \
            if (_d < kd[_m]) {                                             \
                float _td = kd[_m]; kd[_m] = _d; _d = _td;                 \
                int   _tj = ki[_m]; ki[_m] = _j; _j = _tj;                 \
            }                                                              \
        }                                                                  \
    }                                                                      \
} while (0)

__device__ __forceinline__ void cp16(unsigned saddr, const void* g)
{
    asm volatile("cp.async.cg.shared.global [%0], [%1], 16;" :: "r"(saddr), "l"(g));
}

__global__ void __launch_bounds__(256, 1) knn_kernel()
{
    extern __shared__ __align__(16) unsigned sm[];
    float* dstf = (float*)(sm + OFF_DST);

    const int tid  = threadIdx.x;
    const int lane = tid & 31;
    const int wid  = tid >> 5;
    const int wm   = wid >> 2;       // m-block of 64 rows
    const int wn   = wid & 3;        // n-block of 32 cols
    const unsigned smbase = (unsigned)__cvta_generic_to_shared(sm);

    // ---- initial loads: A block + B tile 0 + sq 0 ----
    {
        const uint4* gA = (const uint4*)(g_Af + blockIdx.x * 4096);
        #pragma unroll
        for (int i = 0; i < 4; i++)
            cp16(smbase + (i * 256 + tid) * 16, gA + i * 256 + tid);
        const uint4* gB = (const uint4*)(g_Bf);
        #pragma unroll
        for (int i = 0; i < 4; i++)
            cp16(smbase + OFF_B * 4 + (i * 256 + tid) * 16, gB + i * 256 + tid);
        if (tid < 32)
            cp16(smbase + OFF_SQ * 4 + tid * 16, g_sq + tid * 4);
    }
    asm volatile("cp.async.commit_group;");

    float kd[16]; int ki[16];
    #pragma unroll
    for (int m = 0; m < 16; m++) { kd[m] = 1e30f; ki[m] = 0; }

    const int qh = tid & 1;          // which half of the row to scan
    const int qq = tid >> 1;         // query row

    for (int jt = 0; jt < NBLK; jt++) {
        const int cur = jt & 1;
        // ---- prefetch next B tile (overlaps with MMA + scan) ----
        if (jt + 1 < NBLK) {
            const uint4* gB = (const uint4*)(g_Bf + (jt + 1) * 4096);
            #pragma unroll
            for (int i = 0; i < 4; i++)
                cp16(smbase + (OFF_B + ((jt + 1) & 1) * 4096) * 4 + (i * 256 + tid) * 16,
                     gB + i * 256 + tid);
            if (tid < 32)
                cp16(smbase + (OFF_SQ + ((jt + 1) & 1) * 128) * 4 + tid * 16,
                     g_sq + (jt + 1) * 128 + tid * 4);
        }
        asm volatile("cp.async.commit_group;");
        asm volatile("cp.async.wait_group 1;");
        __syncthreads();

        // ---- MMA: 4 k-steps, hi x hi ----
        float acc[4][4][4];
        #pragma unroll
        for (int mi = 0; mi < 4; mi++)
            #pragma unroll
            for (int ni = 0; ni < 4; ni++)
                #pragma unroll
                for (int r = 0; r < 4; r++) acc[mi][ni][r] = 0.f;

        #pragma unroll
        for (int ks = 0; ks < 4; ks++) {
            const uint4* Ab = (const uint4*)(sm + (ks * 8 + wm * 4) * 128);
            const uint2* Bb = (const uint2*)(sm + OFF_B + cur * 4096 +
                                             (ks * 16 + wn * 4) * 64);
            unsigned a[4][4], b[4][2];
            #pragma unroll
            for (int mi = 0; mi < 4; mi++) {
                uint4 t = Ab[mi * 32 + lane];
                a[mi][0] = t.x; a[mi][1] = t.y; a[mi][2] = t.z; a[mi][3] = t.w;
            }
            #pragma unroll
            for (int ni = 0; ni < 4; ni++) {
                uint2 t = Bb[ni * 32 + lane];
                b[ni][0] = t.x; b[ni][1] = t.y;
            }
            #pragma unroll
            for (int mi = 0; mi < 4; mi++)
                #pragma unroll
                for (int ni = 0; ni < 4; ni++)
                    asm volatile(
                        "mma.sync.aligned.m16n8k16.row.col.f32.bf16.bf16.f32 "
                        "{%0,%1,%2,%3}, {%4,%5,%6,%7}, {%8,%9}, {%0,%1,%2,%3};"
                        : "+f"(acc[mi][ni][0]), "+f"(acc[mi][ni][1]),
                          "+f"(acc[mi][ni][2]), "+f"(acc[mi][ni][3])
                        : "r"(a[mi][0]), "r"(a[mi][1]), "r"(a[mi][2]), "r"(a[mi][3]),
                          "r"(b[ni][0]), "r"(b[ni][1]));
        }

        // ---- epilogue: score = 0.5*|xj|^2 - dot, stage to smem ----
        const float* sqb = (const float*)(sm + OFF_SQ + cur * 128);
        const int g  = lane >> 2;
        const int c2 = (lane & 3) * 2;
        #pragma unroll
        for (int mi = 0; mi < 4; mi++) {
            #pragma unroll
            for (int ni = 0; ni < 4; ni++) {
                int row = (wm * 4 + mi) * 16 + g;
                int col = (wn * 4 + ni) * 8 + c2;
                float q0 = 0.5f * sqb[col], q1 = 0.5f * sqb[col + 1];
                float2 s0 = make_float2(q0 - acc[mi][ni][0], q1 - acc[mi][ni][1]);
                float2 s1 = make_float2(q0 - acc[mi][ni][2], q1 - acc[mi][ni][3]);
                *(float2*)&dstf[row * DSTR + col] = s0;
                *(float2*)&dstf[(row + 8) * DSTR + col] = s1;
            }
        }
        __syncthreads();

        // ---- scan my 64-wide half-row with quad-min guard ----
        const int j0 = jt * 128;
        float thr = kd[15];
        #pragma unroll
        for (int m4 = 0; m4 < 16; m4++) {
            float4 v = *(const float4*)&dstf[qq * DSTR + qh * 64 + m4 * 4];
            float mn = fminf(fminf(v.x, v.y), fminf(v.z, v.w));
            if (mn < thr) {
                int jb = j0 + qh * 64 + m4 * 4;
                TOPK_INSERT(v.x, jb + 0);
                TOPK_INSERT(v.y, jb + 1);
                TOPK_INSERT(v.z, jb + 2);
                TOPK_INSERT(v.w, jb + 3);
                thr = kd[15];
            }
        }
        __syncthreads();
    }

    // ---- dump candidates directly (order irrelevant; refine re-scores) ----
    {
        const int q = blockIdx.x * 128 + qq;
        int* cd = g_cand + q * NCAND + qh * 16;
        #pragma unroll
        for (int m = 0; m < 16; m++) cd[m] = ki[m];
    }
}

// =================================================================
// refine: exact fp32 re-score of 32 candidates, select true top-16.
// 4 queries per block (1 warp each), lane = candidate.
// =================================================================
__global__ void __launch_bounds__(128) refine_kernel(const float* __restrict__ x)
{
    __shared__ float xi[4][64];
    const int tid = threadIdx.x;
    const int w   = tid >> 5, lane = tid & 31;
    const int q0  = blockIdx.x * 4;

    #pragma unroll
    for (int r = 0; r < 2; r++) {
        int li = r * 128 + tid;
        xi[li >> 6][li & 63] = x[q0 * 64 + li];
    }
    __syncthreads();

    const int q = q0 + w;
    const int cj = g_cand[q * NCAND + lane];
    const float4* xr = (const float4*)(x + cj * 64);
    float dot = 0.f;
    #pragma unroll
    for (int i = 0; i < 16; i++) {
        float4 v = xr[i];
        dot = fmaf(xi[w][i * 4 + 0], v.x, dot);
        dot = fmaf(xi[w][i * 4 + 1], v.y, dot);
        dot = fmaf(xi[w][i * 4 + 2], v.z, dot);
        dot = fmaf(xi[w][i * 4 + 3], v.w, dot);
    }
    float s = fmaf(0.5f, g_sq[cj], -dot);

    int rank = 0;
    #pragma unroll
    for (int m = 0; m < NCAND; m++) {
        float sv = __shfl_sync(0xffffffffu, s, m);
        rank += (sv < s) || (sv == s && m < lane);
    }
    if (rank < KNN)
        g_idx[q * KNN + rank] = cj;
}

// =================================================================
// aggregate: s = mean_k relu(base + Bv[j_k]);  out = s @ W2 + b2
// 8 points per block, 128 threads (o = tid), W2 read coalesced.
// =================================================================
__global__ void __launch_bounds__(128) aggregate_kernel(
    const float* __restrict__ W2, const float* __restrict__ b2,
    float* __restrict__ out)
{
    const int n0  = blockIdx.x * 8;
    const int tid = threadIdx.x;
    __shared__ float ss[8][128];
    __shared__ int sidx[128];

    sidx[tid] = g_idx[n0 * 16 + tid];
    __syncthreads();

    #pragma unroll
    for (int p = 0; p < 8; p++) {
        float bv  = g_base[(n0 + p) * 128 + tid];
        float acc = 0.f;
        #pragma unroll
        for (int k = 0; k < 16; k++) {
            float v = bv + g_Bv[sidx[p * 16 + k] * 128 + tid];
            acc += fmaxf(v, 0.f);
        }
        ss[p][tid] = acc * (1.0f / 16.0f);
    }
    __syncthreads();

    float r[8];
    float bb = b2[tid];
    #pragma unroll
    for (int p = 0; p < 8; p++) r[p] = bb;

    #pragma unroll 4
    for (int i = 0; i < 128; i++) {
        float w = W2[i * 128 + tid];
        #pragma unroll
        for (int p = 0; p < 8; p++)
            r[p] = fmaf(ss[p][i], w, r[p]);
    }
    #pragma unroll
    for (int p = 0; p < 8; p++)
        out[(n0 + p) * 128 + tid] = r[p];
}

// =================================================================
extern "C" void kernel_launch(void* const* d_in, const int* in_sizes, int n_in,
                              void* d_out, int out_size)
{
    const float* x  = (const float*)d_in[0];
    const float* W1 = (const float*)d_in[1];
    const float* b1 = (const float*)d_in[2];
    const float* W2 = (const float*)d_in[3];
    const float* b2 = (const float*)d_in[4];
    float* out = (float*)d_out;

    cudaFuncSetAttribute(knn_kernel,
                         cudaFuncAttributeMaxDynamicSharedMemorySize, SM_BYTES);

    precompute_kernel<<<NPTS / 4, 128>>>(x, W1, b1);
    fragpack_kernel<<<NBLK, 256>>>(x);
    knn_kernel<<<NBLK, 256, SM_BYTES>>>();
    refine_kernel<<<NPTS / 4, 128>>>(x);
    aggregate_kernel<<<NPTS / 8, 128>>>(W2, b2, out);
}

// round 7
// speedup vs baseline: 2.5539x; 1.3835x over previous
#include <cuda_runtime.h>
#include <cuda_bf16.h>
#include <cstdint>

#define NPTS 16384
#define ODIM 128
#define KNN  16
#define NCAND 32
#define NBLK 128          // 16384 / 128

// ---------------- scratch (no allocation allowed) ----------------
__device__ float g_base[NPTS * ODIM];              // x @ (W1a - W1b) + b1
__device__ float g_Bv[NPTS * ODIM];                // x @ W1b
__device__ __align__(16) float g_sq[NPTS];         // |x|^2
__device__ int   g_idx[NPTS * KNN];                // final knn indices
__device__ int   g_cand[NPTS * NCAND];             // coarse candidates (unsorted)
__device__ __align__(16) unsigned g_Af[NBLK * 4096];  // A fragments (bf16 hi)
__device__ __align__(16) unsigned g_Bf[NBLK * 4096];  // B fragments (bf16 hi)

// =================================================================
// precompute: base, Bv, sq.  4 points per block, 128 threads (o=tid)
// =================================================================
__global__ void __launch_bounds__(128) precompute_kernel(
    const float* __restrict__ x, const float* __restrict__ W1,
    const float* __restrict__ b1)
{
    const int n0  = blockIdx.x * 4;
    const int tid = threadIdx.x;
    __shared__ float xs[4][64];

    #pragma unroll
    for (int r = 0; r < 2; r++) {
        int li = r * 128 + tid;
        xs[li >> 6][li & 63] = x[n0 * 64 + li];
    }
    __syncthreads();

    float a1[4] = {0.f, 0.f, 0.f, 0.f};
    float a2[4] = {0.f, 0.f, 0.f, 0.f};
    #pragma unroll 4
    for (int c = 0; c < 64; c++) {
        float wa = W1[c * 128 + tid];
        float wb = W1[(64 + c) * 128 + tid];
        float wd = wa - wb;
        #pragma unroll
        for (int nn = 0; nn < 4; nn++) {
            float xv = xs[nn][c];
            a1[nn] = fmaf(xv, wd, a1[nn]);
            a2[nn] = fmaf(xv, wb, a2[nn]);
        }
    }
    float bb = b1[tid];
    #pragma unroll
    for (int nn = 0; nn < 4; nn++) {
        g_base[(n0 + nn) * 128 + tid] = a1[nn] + bb;
        g_Bv[(n0 + nn) * 128 + tid]  = a2[nn];
    }

    int w = tid >> 5, lane = tid & 31;
    float v = xs[w][lane] * xs[w][lane] + xs[w][lane + 32] * xs[w][lane + 32];
    #pragma unroll
    for (int off = 16; off > 0; off >>= 1)
        v += __shfl_xor_sync(0xffffffffu, v, off);
    if (lane == 0) g_sq[n0 + w] = v;
}

// =================================================================
// fragpack: bf16(hi) of x into mma fragment order (per 128-pt block).
// =================================================================
__global__ void __launch_bounds__(256) fragpack_kernel(const float* __restrict__ x)
{
    __shared__ unsigned sA[4096];
    __shared__ unsigned sB[4096];

    const int blk = blockIdx.x;
    const int tid = threadIdx.x;
    const int rl  = tid >> 1;
    const int c0  = (tid & 1) * 32;

    float v[32];
    const float4* xr = (const float4*)(x + (blk * 128 + rl) * 64 + c0);
    #pragma unroll
    for (int i = 0; i < 8; i++) {
        float4 t = xr[i];
        v[i * 4 + 0] = t.x; v[i * 4 + 1] = t.y;
        v[i * 4 + 2] = t.z; v[i * 4 + 3] = t.w;
    }

    const int mt = rl >> 4, gid = rl & 7, r0 = (rl >> 3) & 1;
    const int nt = rl >> 3;
    const int l  = gid * 4;

    #pragma unroll
    for (int cc = 0; cc < 32; cc += 2) {
        int c = c0 + cc;
        __nv_bfloat16 h0 = __float2bfloat16(v[cc]);
        __nv_bfloat16 h1 = __float2bfloat16(v[cc + 1]);
        unsigned uhi = ((unsigned)__bfloat16_as_ushort(h1) << 16) | __bfloat16_as_ushort(h0);

        int ks = c >> 4, cb = (c >> 1) & 3, r1 = (c >> 3) & 1;
        int la = l + cb;
        int rA = r1 * 2 + r0;
        sA[(ks * 8 + mt) * 128 + la * 4 + rA] = uhi;
        sB[(ks * 16 + nt) * 64 + la * 2 + r1] = uhi;
    }
    __syncthreads();

    uint4* dA = (uint4*)(g_Af + blk * 4096);
    uint4* dB = (uint4*)(g_Bf + blk * 4096);
    const uint4* s4A = (const uint4*)sA;
    const uint4* s4B = (const uint4*)sB;
    #pragma unroll
    for (int i = 0; i < 4; i++) {
        dA[i * 256 + tid] = s4A[i * 256 + tid];
        dB[i * 256 + tid] = s4B[i * 256 + tid];
    }
}

// =================================================================
// coarse kNN via bf16 mma.sync (hi-only, fp32 accum).
// CTA: 128 queries x 128-j tiles. 8 warps, each 64x32.
// 2 threads/query each keep top-16 of their half (R3-form scan).
// =================================================================
#define OFF_B   4096            // B double buffer: 2 x 4096 u32
#define OFF_SQ  12288           // 2 x 128 floats
#define OFF_DST 12544           // 128 x 132 floats
#define SM_U32  29440
#define SM_BYTES (SM_U32 * 4)
#define DSTR 132

#define TOPK_INSERT(valx, jjx) do {                                        \
    float _d = (valx); int _j = (jjx);                                     \
    if (_d < kd[15]) {                                                     \
        _Pragma("unroll")                                                  \
        for (int _m = 0; _m < 16; _m++) {                                  \
            if (_d < kd[_m]) {                                             \
                float _td = kd[_m]; kd[_m] = _d; _d = _td;                 \
                int   _tj = ki[_m]; ki[_m] = _j; _j = _tj;                 \
            }                                                              \
        }                                                                  \
    }                                                                      \
} while (0)

__device__ __forceinline__ void cp16(unsigned saddr, const void* g)
{
    asm volatile("cp.async.cg.shared.global [%0], [%1], 16;" :: "r"(saddr), "l"(g));
}

__global__ void __launch_bounds__(256, 1) knn_kernel()
{
    extern __shared__ __align__(16) unsigned sm[];
    float* dstf = (float*)(sm + OFF_DST);

    const int tid  = threadIdx.x;
    const int lane = tid & 31;
    const int wid  = tid >> 5;
    const int wm   = wid >> 2;       // m-block of 64 rows
    const int wn   = wid & 3;        // n-block of 32 cols
    const unsigned smbase = (unsigned)__cvta_generic_to_shared(sm);

    // ---- initial loads: A block + B tile 0 + sq 0 ----
    {
        const uint4* gA = (const uint4*)(g_Af + blockIdx.x * 4096);
        #pragma unroll
        for (int i = 0; i < 4; i++)
            cp16(smbase + (i * 256 + tid) * 16, gA + i * 256 + tid);
        const uint4* gB = (const uint4*)(g_Bf);
        #pragma unroll
        for (int i = 0; i < 4; i++)
            cp16(smbase + OFF_B * 4 + (i * 256 + tid) * 16, gB + i * 256 + tid);
        if (tid < 32)
            cp16(smbase + OFF_SQ * 4 + tid * 16, g_sq + tid * 4);
    }
    asm volatile("cp.async.commit_group;");

    float kd[16]; int ki[16];
    #pragma unroll
    for (int m = 0; m < 16; m++) { kd[m] = 1e30f; ki[m] = 0; }

    const int qh = tid & 1;          // which half of the row to scan
    const int qq = tid >> 1;         // query row

    for (int jt = 0; jt < NBLK; jt++) {
        const int cur = jt & 1;
        // ---- prefetch next B tile (overlaps with MMA + scan) ----
        if (jt + 1 < NBLK) {
            const uint4* gB = (const uint4*)(g_Bf + (jt + 1) * 4096);
            #pragma unroll
            for (int i = 0; i < 4; i++)
                cp16(smbase + (OFF_B + ((jt + 1) & 1) * 4096) * 4 + (i * 256 + tid) * 16,
                     gB + i * 256 + tid);
            if (tid < 32)
                cp16(smbase + (OFF_SQ + ((jt + 1) & 1) * 128) * 4 + tid * 16,
                     g_sq + (jt + 1) * 128 + tid * 4);
        }
        asm volatile("cp.async.commit_group;");
        asm volatile("cp.async.wait_group 1;");
        __syncthreads();

        // ---- MMA: 4 k-steps, hi x hi ----
        float acc[4][4][4];
        #pragma unroll
        for (int mi = 0; mi < 4; mi++)
            #pragma unroll
            for (int ni = 0; ni < 4; ni++)
                #pragma unroll
                for (int r = 0; r < 4; r++) acc[mi][ni][r] = 0.f;

        #pragma unroll
        for (int ks = 0; ks < 4; ks++) {
            const uint4* Ab = (const uint4*)(sm + (ks * 8 + wm * 4) * 128);
            const uint2* Bb = (const uint2*)(sm + OFF_B + cur * 4096 +
                                             (ks * 16 + wn * 4) * 64);
            unsigned a[4][4], b[4][2];
            #pragma unroll
            for (int mi = 0; mi < 4; mi++) {
                uint4 t = Ab[mi * 32 + lane];
                a[mi][0] = t.x; a[mi][1] = t.y; a[mi][2] = t.z; a[mi][3] = t.w;
            }
            #pragma unroll
            for (int ni = 0; ni < 4; ni++) {
                uint2 t = Bb[ni * 32 + lane];
                b[ni][0] = t.x; b[ni][1] = t.y;
            }
            #pragma unroll
            for (int mi = 0; mi < 4; mi++)
                #pragma unroll
                for (int ni = 0; ni < 4; ni++)
                    asm volatile(
                        "mma.sync.aligned.m16n8k16.row.col.f32.bf16.bf16.f32 "
                        "{%0,%1,%2,%3}, {%4,%5,%6,%7}, {%8,%9}, {%0,%1,%2,%3};"
                        : "+f"(acc[mi][ni][0]), "+f"(acc[mi][ni][1]),
                          "+f"(acc[mi][ni][2]), "+f"(acc[mi][ni][3])
                        : "r"(a[mi][0]), "r"(a[mi][1]), "r"(a[mi][2]), "r"(a[mi][3]),
                          "r"(b[ni][0]), "r"(b[ni][1]));
        }

        // ---- epilogue: score = 0.5*|xj|^2 - dot, stage to smem ----
        const float* sqb = (const float*)(sm + OFF_SQ + cur * 128);
        const int g  = lane >> 2;
        const int c2 = (lane & 3) * 2;
        #pragma unroll
        for (int mi = 0; mi < 4; mi++) {
            #pragma unroll
            for (int ni = 0; ni < 4; ni++) {
                int row = (wm * 4 + mi) * 16 + g;
                int col = (wn * 4 + ni) * 8 + c2;
                float q0 = 0.5f * sqb[col], q1 = 0.5f * sqb[col + 1];
                float2 s0 = make_float2(q0 - acc[mi][ni][0], q1 - acc[mi][ni][1]);
                float2 s1 = make_float2(q0 - acc[mi][ni][2], q1 - acc[mi][ni][3]);
                *(float2*)&dstf[row * DSTR + col] = s0;
                *(float2*)&dstf[(row + 8) * DSTR + col] = s1;
            }
        }
        __syncthreads();

        // ---- scan my 64-wide half-row (R3 form: no guard, no branch) ----
        const int j0 = jt * 128;
        #pragma unroll
        for (int m4 = 0; m4 < 16; m4++) {
            float4 v = *(const float4*)&dstf[qq * DSTR + qh * 64 + m4 * 4];
            int jb = j0 + qh * 64 + m4 * 4;
            TOPK_INSERT(v.x, jb + 0);
            TOPK_INSERT(v.y, jb + 1);
            TOPK_INSERT(v.z, jb + 2);
            TOPK_INSERT(v.w, jb + 3);
        }
        __syncthreads();
    }

    // ---- dump candidates directly (order irrelevant; refine re-scores) ----
    {
        const int q = blockIdx.x * 128 + qq;
        int* cd = g_cand + q * NCAND + qh * 16;
        #pragma unroll
        for (int m = 0; m < 16; m++) cd[m] = ki[m];
    }
}

// =================================================================
// refine: exact fp32 re-score of 32 candidates, select true top-16.
// 4 queries per block (1 warp each), lane = candidate.
// =================================================================
__global__ void __launch_bounds__(128) refine_kernel(const float* __restrict__ x)
{
    __shared__ float xi[4][64];
    const int tid = threadIdx.x;
    const int w   = tid >> 5, lane = tid & 31;
    const int q0  = blockIdx.x * 4;

    #pragma unroll
    for (int r = 0; r < 2; r++) {
        int li = r * 128 + tid;
        xi[li >> 6][li & 63] = x[q0 * 64 + li];
    }
    __syncthreads();

    const int q = q0 + w;
    const int cj = g_cand[q * NCAND + lane];
    const float4* xr = (const float4*)(x + cj * 64);
    float dot = 0.f;
    #pragma unroll
    for (int i = 0; i < 16; i++) {
        float4 v = xr[i];
        dot = fmaf(xi[w][i * 4 + 0], v.x, dot);
        dot = fmaf(xi[w][i * 4 + 1], v.y, dot);
        dot = fmaf(xi[w][i * 4 + 2], v.z, dot);
        dot = fmaf(xi[w][i * 4 + 3], v.w, dot);
    }
    float s = fmaf(0.5f, g_sq[cj], -dot);

    int rank = 0;
    #pragma unroll
    for (int m = 0; m < NCAND; m++) {
        float sv = __shfl_sync(0xffffffffu, s, m);
        rank += (sv < s) || (sv == s && m < lane);
    }
    if (rank < KNN)
        g_idx[q * KNN + rank] = cj;
}

// =================================================================
// aggregate: s = mean_k relu(base + Bv[j_k]);  out = s @ W2 + b2
// 8 points per block, 128 threads (o = tid), W2 read coalesced.
// =================================================================
__global__ void __launch_bounds__(128) aggregate_kernel(
    const float* __restrict__ W2, const float* __restrict__ b2,
    float* __restrict__ out)
{
    const int n0  = blockIdx.x * 8;
    const int tid = threadIdx.x;
    __shared__ float ss[8][128];
    __shared__ int sidx[128];

    sidx[tid] = g_idx[n0 * 16 + tid];
    __syncthreads();

    #pragma unroll
    for (int p = 0; p < 8; p++) {
        float bv  = g_base[(n0 + p) * 128 + tid];
        float acc = 0.f;
        #pragma unroll
        for (int k = 0; k < 16; k++) {
            float v = bv + g_Bv[sidx[p * 16 + k] * 128 + tid];
            acc += fmaxf(v, 0.f);
        }
        ss[p][tid] = acc * (1.0f / 16.0f);
    }
    __syncthreads();

    float r[8];
    float bb = b2[tid];
    #pragma unroll
    for (int p = 0; p < 8; p++) r[p] = bb;

    #pragma unroll 4
    for (int i = 0; i < 128; i++) {
        float w = W2[i * 128 + tid];
        #pragma unroll
        for (int p = 0; p < 8; p++)
            r[p] = fmaf(ss[p][i], w, r[p]);
    }
    #pragma unroll
    for (int p = 0; p < 8; p++)
        out[(n0 + p) * 128 + tid] = r[p];
}

// =================================================================
extern "C" void kernel_launch(void* const* d_in, const int* in_sizes, int n_in,
                              void* d_out, int out_size)
{
    const float* x  = (const float*)d_in[0];
    const float* W1 = (const float*)d_in[1];
    const float* b1 = (const float*)d_in[2];
    const float* W2 = (const float*)d_in[3];
    const float* b2 = (const float*)d_in[4];
    float* out = (float*)d_out;

    cudaFuncSetAttribute(knn_kernel,
                         cudaFuncAttributeMaxDynamicSharedMemorySize, SM_BYTES);

    precompute_kernel<<<NPTS / 4, 128>>>(x, W1, b1);
    fragpack_kernel<<<NBLK, 256>>>(x);
    knn_kernel<<<NBLK, 256, SM_BYTES>>>();
    refine_kernel<<<NPTS / 4, 128>>>(x);
    aggregate_kernel<<<NPTS / 8, 128>>>(W2, b2, out);
}